// round 9
// baseline (speedup 1.0000x reference)
#include <cuda_runtime.h>
#include <cuda_bf16.h>
#include <math.h>
#include <float.h>
#include <stdint.h>

// Problem constants
#define BATCH 16
#define PAIRS 8
#define NPTS  2048
#define DIM   256

// proj GEMM tiling
#define BM 128
#define BN 128
#define BKH 32
#define SW 20

// ---------------- device scratch ----------------
__device__ unsigned char g_mdesc8[(size_t)BATCH * NPTS * DIM];    // 8.4 MB (e4m3 m_desc)
__device__ __nv_bfloat16 g_Sh[(size_t)PAIRS * NPTS * NPTS];       // 67 MB (bf16 S)
__device__ float  g_lsP[BATCH * NPTS];
__device__ float  g_lsN[BATCH * NPTS];
__device__ float  g_rowS[PAIRS * NPTS];
__device__ float  g_colS[PAIRS * NPTS];
__device__ float2 g_rr[PAIRS * NPTS];
__device__ float2 g_cc[PAIRS * NPTS];

// ---------------- helpers ----------------
__device__ __forceinline__ unsigned pack_bf16(float lo, float hi) {
    unsigned r;
    asm("cvt.rn.bf16x2.f32 %0, %1, %2;" : "=r"(r) : "f"(hi), "f"(lo));
    return r;
}
__device__ __forceinline__ unsigned short pack_e4m3(float lo, float hi) {
    unsigned short r;
    asm("cvt.rn.satfinite.e4m3x2.f32 %0, %1, %2;" : "=h"(r) : "f"(hi), "f"(lo));
    return r;
}

__device__ __forceinline__ void mma_bf16(float c[4], const unsigned a[4], const unsigned b[2]) {
    asm volatile(
        "mma.sync.aligned.m16n8k16.row.col.f32.bf16.bf16.f32 "
        "{%0,%1,%2,%3},{%4,%5,%6,%7},{%8,%9},{%0,%1,%2,%3};"
        : "+f"(c[0]), "+f"(c[1]), "+f"(c[2]), "+f"(c[3])
        : "r"(a[0]), "r"(a[1]), "r"(a[2]), "r"(a[3]), "r"(b[0]), "r"(b[1]));
}

__device__ __forceinline__ void mma_fp8(float c[4], const unsigned a[4], const unsigned b[2]) {
    asm volatile(
        "mma.sync.aligned.m16n8k32.row.col.f32.e4m3.e4m3.f32 "
        "{%0,%1,%2,%3},{%4,%5,%6,%7},{%8,%9},{%0,%1,%2,%3};"
        : "+f"(c[0]), "+f"(c[1]), "+f"(c[2]), "+f"(c[3])
        : "r"(a[0]), "r"(a[1]), "r"(a[2]), "r"(a[3]), "r"(b[0]), "r"(b[1]));
}

__device__ __forceinline__ float logsigmoidf(float x) {
    return fminf(x, 0.f) - log1pf(expf(-fabsf(x)));
}

__device__ __forceinline__ float warpSum(float v) {
    #pragma unroll
    for (int o = 16; o > 0; o >>= 1) v += __shfl_xor_sync(0xffffffffu, v, o);
    return v;
}

// ---------------- K0: zero accumulators ----------------
__global__ __launch_bounds__(256) void init_kernel() {
    int i = blockIdx.x * 256 + threadIdx.x;
    if (i < PAIRS * NPTS) { g_rowS[i] = 0.f; g_colS[i] = 0.f; }
}

// ---------------- K1: projection GEMM (fp32 in -> bf16 mma -> e4m3 out) ----------------
__global__ __launch_bounds__(256) void proj_gemm(const float* __restrict__ A,
                                                 const float* __restrict__ W,
                                                 const float* __restrict__ bias) {
    __shared__ unsigned sA[BM][SW];
    __shared__ unsigned sB[BN][SW];

    const int tid = threadIdx.x;
    const int wid = tid >> 5, lane = tid & 31;
    const int wm = wid >> 2, wn = wid & 3;
    const int g = lane >> 2, t = lane & 3;

    const int rowBase = blockIdx.y * BM;
    const int colBase = blockIdx.x * BN;

    float acc[4][4][4];
    #pragma unroll
    for (int mi = 0; mi < 4; mi++)
        #pragma unroll
        for (int ni = 0; ni < 4; ni++)
            #pragma unroll
            for (int e = 0; e < 4; e++) acc[mi][ni][e] = 0.f;

    for (int kb = 0; kb < DIM; kb += BKH) {
        #pragma unroll
        for (int i = 0; i < 4; i++) {
            int idx = tid + i * 256;
            int r = idx >> 3;
            int c4 = idx & 7;
            float4 va = *(const float4*)(A + (size_t)(rowBase + r) * DIM + kb + c4 * 4);
            sA[r][c4 * 2 + 0] = pack_bf16(va.x, va.y);
            sA[r][c4 * 2 + 1] = pack_bf16(va.z, va.w);
            float4 vb = *(const float4*)(W + (size_t)(colBase + r) * DIM + kb + c4 * 4);
            sB[r][c4 * 2 + 0] = pack_bf16(vb.x, vb.y);
            sB[r][c4 * 2 + 1] = pack_bf16(vb.z, vb.w);
        }
        __syncthreads();

        #pragma unroll
        for (int ks = 0; ks < 2; ks++) {
            const int j0 = ks * 8;
            unsigned a[4][4], b[4][2];
            #pragma unroll
            for (int mi = 0; mi < 4; mi++) {
                int r0 = wm * 64 + mi * 16 + g;
                a[mi][0] = sA[r0][j0 + t];
                a[mi][1] = sA[r0 + 8][j0 + t];
                a[mi][2] = sA[r0][j0 + t + 4];
                a[mi][3] = sA[r0 + 8][j0 + t + 4];
            }
            #pragma unroll
            for (int ni = 0; ni < 4; ni++) {
                int c0 = wn * 32 + ni * 8 + g;
                b[ni][0] = sB[c0][j0 + t];
                b[ni][1] = sB[c0][j0 + t + 4];
            }
            #pragma unroll
            for (int mi = 0; mi < 4; mi++)
                #pragma unroll
                for (int ni = 0; ni < 4; ni++)
                    mma_bf16(acc[mi][ni], a[mi], b[ni]);
        }
        __syncthreads();
    }

    #pragma unroll
    for (int mi = 0; mi < 4; mi++) {
        #pragma unroll
        for (int ni = 0; ni < 4; ni++) {
            #pragma unroll
            for (int eh = 0; eh < 2; eh++) {
                int row = rowBase + wm * 64 + mi * 16 + g + eh * 8;
                int col = colBase + wn * 32 + ni * 8 + 2 * t;
                float v0 = (acc[mi][ni][eh * 2 + 0] + bias[col])     * 0.25f;
                float v1 = (acc[mi][ni][eh * 2 + 1] + bias[col + 1]) * 0.25f;
                *(unsigned short*)&g_mdesc8[(size_t)row * DIM + col] = pack_e4m3(v0, v1);
            }
        }
    }
}

// ---------------- K2: similarity GEMM (fp8, double-buffered) + fused epilogue ----------------
// k-block = 64 fp8 = two k32 sub-steps. Per stage per operand: 2 subs x 128 rows x 48B (12KB).
// Row layout within a sub: 32B data padded to 48B (12 words) -> conflict-free frag LDS.
#define SUBW 1536                 // words per k32 sub (128 * 12)
#define STAGEW (2 * SUBW)         // words per stage per operand (12 KB)
#define SIM_NKB 4                 // 256 / 64
#define SIM_SMEM (4 * STAGEW * 4) // A/B x 2 stages = 49152 B

__global__ __launch_bounds__(256, 2) void sim_gemm(const int* __restrict__ mask) {
    extern __shared__ unsigned dsmw[];
    unsigned* sAw = dsmw;                 // [2][STAGEW]
    unsigned* sBw = dsmw + 2 * STAGEW;    // [2][STAGEW]
    __shared__ float sRow[BM];
    __shared__ float sCol[BN];

    const int tid = threadIdx.x;
    const int wid = tid >> 5, lane = tid & 31;
    const int wm = wid >> 2, wn = wid & 3;
    const int g = lane >> 2, t = lane & 3;

    const int p = blockIdx.z;
    const int rowBase = blockIdx.y * BM;
    const int colBase = blockIdx.x * BN;

    const unsigned char* Ap = g_mdesc8 + (size_t)(2 * p) * NPTS * DIM + (size_t)rowBase * DIM;
    const unsigned char* Bp = g_mdesc8 + (size_t)(2 * p + 1) * NPTS * DIM + (size_t)colBase * DIM;

    if (tid < BM) sRow[tid] = 0.f;
    else sCol[tid - BM] = 0.f;

    // staging: thread -> (row, 16B-half); per k-block loads 2 subs x 16B per operand
    const int r_ld = tid >> 1;
    const int h_ld = tid & 1;
    const unsigned char* Ag = Ap + r_ld * DIM + h_ld * 16;
    const unsigned char* Bg = Bp + r_ld * DIM + h_ld * 16;
    const int wst = r_ld * 12 + h_ld * 4;         // word offset within a sub

    float acc[4][4][4];
    #pragma unroll
    for (int mi = 0; mi < 4; mi++)
        #pragma unroll
        for (int ni = 0; ni < 4; ni++)
            #pragma unroll
            for (int e = 0; e < 4; e++) acc[mi][ni][e] = 0.f;

    uint4 aa[2], bb[2];
    // prologue: load kb=0
    #pragma unroll
    for (int j = 0; j < 2; j++) {
        aa[j] = *(const uint4*)(Ag + j * 32);
        bb[j] = *(const uint4*)(Bg + j * 32);
    }
    #pragma unroll
    for (int j = 0; j < 2; j++) {
        *(uint4*)&sAw[j * SUBW + wst] = aa[j];
        *(uint4*)&sBw[j * SUBW + wst] = bb[j];
    }
    __syncthreads();

    for (int kb = 0; kb < SIM_NKB; kb++) {
        const int cur = kb & 1;
        if (kb + 1 < SIM_NKB) {
            #pragma unroll
            for (int j = 0; j < 2; j++) {
                aa[j] = *(const uint4*)(Ag + (kb + 1) * 64 + j * 32);
                bb[j] = *(const uint4*)(Bg + (kb + 1) * 64 + j * 32);
            }
        }

        #pragma unroll
        for (int j = 0; j < 2; j++) {
            const unsigned* As = sAw + cur * STAGEW + j * SUBW;
            const unsigned* Bs = sBw + cur * STAGEW + j * SUBW;
            unsigned a[4][4], b[4][2];
            #pragma unroll
            for (int mi = 0; mi < 4; mi++) {
                int r0 = wm * 64 + mi * 16 + g;
                a[mi][0] = As[r0 * 12 + t];
                a[mi][1] = As[(r0 + 8) * 12 + t];
                a[mi][2] = As[r0 * 12 + t + 4];
                a[mi][3] = As[(r0 + 8) * 12 + t + 4];
            }
            #pragma unroll
            for (int ni = 0; ni < 4; ni++) {
                int c0 = wn * 32 + ni * 8 + g;
                b[ni][0] = Bs[c0 * 12 + t];
                b[ni][1] = Bs[c0 * 12 + t + 4];
            }
            #pragma unroll
            for (int mi = 0; mi < 4; mi++)
                #pragma unroll
                for (int ni = 0; ni < 4; ni++)
                    mma_fp8(acc[mi][ni], a[mi], b[ni]);
        }

        if (kb + 1 < SIM_NKB) {
            const int nxt = (kb + 1) & 1;
            #pragma unroll
            for (int j = 0; j < 2; j++) {
                *(uint4*)&sAw[nxt * STAGEW + j * SUBW + wst] = aa[j];
                *(uint4*)&sBw[nxt * STAGEW + j * SUBW + wst] = bb[j];
            }
            __syncthreads();
        }
    }

    // Epilogue: mask -> bf16 store + exp-sum accumulation (R8-proven)
    const int* m0 = mask + (size_t)(2 * p) * NPTS;
    const int* m1 = mask + (size_t)(2 * p + 1) * NPTS;
    __nv_bfloat16* Sp = g_Sh + (size_t)p * NPTS * NPTS;

    float rowP[4][2];
    float colP[4][2];
    #pragma unroll
    for (int i = 0; i < 4; i++) { rowP[i][0] = rowP[i][1] = 0.f; colP[i][0] = colP[i][1] = 0.f; }

    #pragma unroll
    for (int mi = 0; mi < 4; mi++) {
        int rm[2];
        rm[0] = m0[rowBase + wm * 64 + mi * 16 + g];
        rm[1] = m0[rowBase + wm * 64 + mi * 16 + g + 8];
        #pragma unroll
        for (int ni = 0; ni < 4; ni++) {
            int col = colBase + wn * 32 + ni * 8 + 2 * t;
            int cm0 = m1[col], cm1 = m1[col + 1];
            #pragma unroll
            for (int eh = 0; eh < 2; eh++) {
                int row = rowBase + wm * 64 + mi * 16 + g + eh * 8;
                float vx = (rm[eh] && cm0) ? acc[mi][ni][eh * 2 + 0] : -FLT_MAX;
                float vy = (rm[eh] && cm1) ? acc[mi][ni][eh * 2 + 1] : -FLT_MAX;
                *(unsigned*)&Sp[(size_t)row * NPTS + col] = pack_bf16(vx, vy);
                float e0 = __expf(vx);
                float e1 = __expf(vy);
                rowP[mi][eh] += e0 + e1;
                colP[ni][0] += e0;
                colP[ni][1] += e1;
            }
        }
    }

    __syncthreads();

    #pragma unroll
    for (int mi = 0; mi < 4; mi++)
        #pragma unroll
        for (int eh = 0; eh < 2; eh++) {
            float r = rowP[mi][eh];
            r += __shfl_xor_sync(0xffffffffu, r, 1);
            r += __shfl_xor_sync(0xffffffffu, r, 2);
            if (t == 0) atomicAdd(&sRow[wm * 64 + mi * 16 + g + eh * 8], r);
        }
    #pragma unroll
    for (int ni = 0; ni < 4; ni++)
        #pragma unroll
        for (int c = 0; c < 2; c++) {
            float v = colP[ni][c];
            v += __shfl_xor_sync(0xffffffffu, v, 4);
            v += __shfl_xor_sync(0xffffffffu, v, 8);
            v += __shfl_xor_sync(0xffffffffu, v, 16);
            if (g == 0) atomicAdd(&sCol[wn * 32 + ni * 8 + 2 * t + c], v);
        }
    __syncthreads();

    if (tid < BM) atomicAdd(&g_rowS[p * NPTS + rowBase + tid], sRow[tid]);
    else          atomicAdd(&g_colS[p * NPTS + colBase + (tid - BM)], sCol[tid - BM]);
}

// ---------------- K_match ----------------
__global__ __launch_bounds__(256) void match_kernel(const float* __restrict__ desc,
                                                    const float* __restrict__ mw,
                                                    const float* __restrict__ mb) {
    int warp = blockIdx.x * 8 + (threadIdx.x >> 5);
    int lane = threadIdx.x & 31;
    const float* dp = desc + (size_t)warp * DIM;
    float acc = 0.f;
    #pragma unroll
    for (int i = 0; i < 8; i++)
        acc = fmaf(dp[lane + 32 * i], mw[lane + 32 * i], acc);
    acc = warpSum(acc);
    if (lane == 0) {
        float m = acc + mb[0];
        g_lsP[warp] = logsigmoidf(m);
        g_lsN[warp] = logsigmoidf(-m);
    }
}

// ---------------- K3: finish rr/cc ----------------
__global__ __launch_bounds__(256) void finish_kernel(const int* __restrict__ mask) {
    int idx = blockIdx.x * 256 + threadIdx.x;
    if (idx >= PAIRS * NPTS) return;
    int p = idx >> 11, i = idx & (NPTS - 1);

    int a0 = mask[(size_t)(2 * p) * NPTS + i];
    float l0 = a0 ? __logf(g_rowS[idx]) : __logf((float)NPTS);
    g_rr[idx] = make_float2(a0 ? 1.f : 0.f, g_lsP[(size_t)(2 * p) * NPTS + i] - l0);

    int a1 = mask[(size_t)(2 * p + 1) * NPTS + i];
    float l1 = a1 ? __logf(g_colS[idx]) : __logf((float)NPTS);
    g_cc[idx] = make_float2(a1 ? 1.f : 0.f, g_lsP[(size_t)(2 * p + 1) * NPTS + i] - l1);
}

// ---------------- K5: final assembly ----------------
#define NOUT (NPTS + 1)
__global__ __launch_bounds__(256) void final_kernel(float* __restrict__ out) {
    const int n = blockIdx.x;
    const int p = blockIdx.y;
    const int tid = threadIdx.x;

    const float2 rr = g_rr[p * NPTS + n];
    const float2* cc = g_cc + p * NPTS;
    const __nv_bfloat16* Srow = g_Sh + ((size_t)p * NPTS + n) * NPTS;
    const float lsN0n = g_lsN[(size_t)(2 * p) * NPTS + n];

    const size_t base = ((size_t)p * NOUT + n) * NOUT;
    const int sh = (int)((4 - (base & 3)) & 3);
    const int K = (NOUT - sh) >> 2;
    const int rem = (NOUT - sh) & 3;

    for (int k = tid; k < K; k += 256) {
        int m0 = sh + 4 * k;
        float4 o;
        float* oc = &o.x;
        #pragma unroll
        for (int c = 0; c < 4; c++) {
            int m = m0 + c;
            if (m < NPTS) {
                float s = __bfloat162float(__ldg(Srow + m));
                if (s < -1e38f) s = -FLT_MAX;
                float2 cm = __ldg(cc + m);
                oc[c] = fmaf(rr.x + cm.x, s, rr.y + cm.y);
            } else {
                oc[c] = lsN0n;
            }
        }
        *(float4*)(out + base + m0) = o;
    }

    if (tid < sh) {
        int m = tid;
        float s = __bfloat162float(__ldg(Srow + m));
        if (s < -1e38f) s = -FLT_MAX;
        float2 cm = __ldg(cc + m);
        out[base + m] = fmaf(rr.x + cm.x, s, rr.y + cm.y);
    } else if (tid >= 4 && tid < 4 + rem) {
        int m = sh + 4 * K + (tid - 4);
        float v;
        if (m < NPTS) {
            float s = __bfloat162float(__ldg(Srow + m));
            if (s < -1e38f) s = -FLT_MAX;
            float2 cm = __ldg(cc + m);
            v = fmaf(rr.x + cm.x, s, rr.y + cm.y);
        } else {
            v = lsN0n;
        }
        out[base + m] = v;
    }
}

__global__ __launch_bounds__(256) void border_kernel(float* __restrict__ out) {
    int m = blockIdx.x * 256 + threadIdx.x;
    int p = blockIdx.y;
    if (m >= NOUT) return;
    float v = (m < NPTS) ? g_lsN[(size_t)(2 * p + 1) * NPTS + m] : 0.f;
    out[((size_t)p * NOUT + NPTS) * NOUT + m] = v;
}

// ---------------- launch ----------------
extern "C" void kernel_launch(void* const* d_in, const int* in_sizes, int n_in,
                              void* d_out, int out_size) {
    const float* descriptors = (const float*)d_in[0];
    const int*   mask        = (const int*)d_in[1];
    const float* proj_w      = (const float*)d_in[2];
    const float* proj_b      = (const float*)d_in[3];
    const float* match_w     = (const float*)d_in[4];
    const float* match_b     = (const float*)d_in[5];
    float* out = (float*)d_out;

    cudaFuncSetAttribute(sim_gemm, cudaFuncAttributeMaxDynamicSharedMemorySize, SIM_SMEM);

    init_kernel<<<(PAIRS * NPTS + 255) / 256, 256>>>();
    proj_gemm<<<dim3(DIM / BN, (BATCH * NPTS) / BM, 1), 256>>>(descriptors, proj_w, proj_b);
    match_kernel<<<(BATCH * NPTS) / 8, 256>>>(descriptors, match_w, match_b);
    sim_gemm<<<dim3(NPTS / BN, NPTS / BM, PAIRS), 256, SIM_SMEM>>>(mask);
    finish_kernel<<<(PAIRS * NPTS + 255) / 256, 256>>>(mask);
    final_kernel<<<dim3(NPTS, PAIRS), 256>>>(out);
    border_kernel<<<dim3((NOUT + 255) / 256, PAIRS), 256>>>(out);
}

// round 10
// speedup vs baseline: 1.4542x; 1.4542x over previous
#include <cuda_runtime.h>
#include <cuda_bf16.h>
#include <math.h>
#include <float.h>
#include <stdint.h>

// Problem constants
#define BATCH 16
#define PAIRS 8
#define NPTS  2048
#define DIM   256

// GEMM tiling
#define BM 128
#define BN 128
#define BKH 32          // bf16 elements per k-block
#define SW 20           // smem row stride in uint32 (16 data + 4 pad) -> conflict-free

// ---------------- device scratch ----------------
__device__ __nv_bfloat16 g_mdescH[(size_t)BATCH * NPTS * DIM];    // 16.8 MB
__device__ __nv_bfloat16 g_Sh[(size_t)PAIRS * NPTS * NPTS];       // 67 MB (bf16 S)
__device__ float  g_lsP[BATCH * NPTS];
__device__ float  g_lsN[BATCH * NPTS];
__device__ float  g_rowS[PAIRS * NPTS];
__device__ float  g_colS[PAIRS * NPTS];
__device__ float2 g_rr[PAIRS * NPTS];
__device__ float2 g_cc[PAIRS * NPTS];

// ---------------- helpers ----------------
__device__ __forceinline__ unsigned pack_bf16(float lo, float hi) {
    unsigned r;
    asm("cvt.rn.bf16x2.f32 %0, %1, %2;" : "=r"(r) : "f"(hi), "f"(lo));
    return r;
}

__device__ __forceinline__ void mma_bf16(float c[4], const unsigned a[4], const unsigned b[2]) {
    asm volatile(
        "mma.sync.aligned.m16n8k16.row.col.f32.bf16.bf16.f32 "
        "{%0,%1,%2,%3},{%4,%5,%6,%7},{%8,%9},{%0,%1,%2,%3};"
        : "+f"(c[0]), "+f"(c[1]), "+f"(c[2]), "+f"(c[3])
        : "r"(a[0]), "r"(a[1]), "r"(a[2]), "r"(a[3]), "r"(b[0]), "r"(b[1]));
}

__device__ __forceinline__ float logsigmoidf(float x) {
    return fminf(x, 0.f) - log1pf(expf(-fabsf(x)));
}

__device__ __forceinline__ float warpSum(float v) {
    #pragma unroll
    for (int o = 16; o > 0; o >>= 1) v += __shfl_xor_sync(0xffffffffu, v, o);
    return v;
}

// ---------------- K1: projection GEMM (fp32 in -> bf16 mma -> bf16 out) ----------------
__global__ __launch_bounds__(256) void proj_gemm(const float* __restrict__ A,
                                                 const float* __restrict__ W,
                                                 const float* __restrict__ bias) {
    __shared__ unsigned sA[BM][SW];
    __shared__ unsigned sB[BN][SW];

    const int tid = threadIdx.x;
    const int wid = tid >> 5, lane = tid & 31;
    const int wm = wid >> 2, wn = wid & 3;
    const int g = lane >> 2, t = lane & 3;

    const int rowBase = blockIdx.y * BM;
    const int colBase = blockIdx.x * BN;

    float acc[4][4][4];
    #pragma unroll
    for (int mi = 0; mi < 4; mi++)
        #pragma unroll
        for (int ni = 0; ni < 4; ni++)
            #pragma unroll
            for (int e = 0; e < 4; e++) acc[mi][ni][e] = 0.f;

    for (int kb = 0; kb < DIM; kb += BKH) {
        #pragma unroll
        for (int i = 0; i < 4; i++) {
            int idx = tid + i * 256;
            int r = idx >> 3;
            int c4 = idx & 7;
            float4 va = *(const float4*)(A + (size_t)(rowBase + r) * DIM + kb + c4 * 4);
            sA[r][c4 * 2 + 0] = pack_bf16(va.x, va.y);
            sA[r][c4 * 2 + 1] = pack_bf16(va.z, va.w);
            float4 vb = *(const float4*)(W + (size_t)(colBase + r) * DIM + kb + c4 * 4);
            sB[r][c4 * 2 + 0] = pack_bf16(vb.x, vb.y);
            sB[r][c4 * 2 + 1] = pack_bf16(vb.z, vb.w);
        }
        __syncthreads();

        #pragma unroll
        for (int ks = 0; ks < 2; ks++) {
            const int j0 = ks * 8;
            unsigned a[4][4], b[4][2];
            #pragma unroll
            for (int mi = 0; mi < 4; mi++) {
                int r0 = wm * 64 + mi * 16 + g;
                a[mi][0] = sA[r0][j0 + t];
                a[mi][1] = sA[r0 + 8][j0 + t];
                a[mi][2] = sA[r0][j0 + t + 4];
                a[mi][3] = sA[r0 + 8][j0 + t + 4];
            }
            #pragma unroll
            for (int ni = 0; ni < 4; ni++) {
                int c0 = wn * 32 + ni * 8 + g;
                b[ni][0] = sB[c0][j0 + t];
                b[ni][1] = sB[c0][j0 + t + 4];
            }
            #pragma unroll
            for (int mi = 0; mi < 4; mi++)
                #pragma unroll
                for (int ni = 0; ni < 4; ni++)
                    mma_bf16(acc[mi][ni], a[mi], b[ni]);
        }
        __syncthreads();
    }

    #pragma unroll
    for (int mi = 0; mi < 4; mi++) {
        #pragma unroll
        for (int ni = 0; ni < 4; ni++) {
            #pragma unroll
            for (int eh = 0; eh < 2; eh++) {
                int row = rowBase + wm * 64 + mi * 16 + g + eh * 8;
                int col = colBase + wn * 32 + ni * 8 + 2 * t;
                float v0 = (acc[mi][ni][eh * 2 + 0] + bias[col])     * 0.25f;
                float v1 = (acc[mi][ni][eh * 2 + 1] + bias[col + 1]) * 0.25f;
                *(unsigned*)&g_mdescH[(size_t)row * DIM + col] = pack_bf16(v0, v1);
            }
        }
    }
}

// ---------------- K2: similarity GEMM + fused mask/exp-sum epilogue (R5 verbatim) ----------------
__global__ __launch_bounds__(256) void sim_gemm(const int* __restrict__ mask) {
    __shared__ unsigned sA[2][BM][SW];
    __shared__ unsigned sB[2][BN][SW];
    __shared__ float sRow[BM];
    __shared__ float sCol[BN];

    const int tid = threadIdx.x;
    const int wid = tid >> 5, lane = tid & 31;
    const int wm = wid >> 2, wn = wid & 3;
    const int g = lane >> 2, t = lane & 3;

    const int p = blockIdx.z;
    const int rowBase = blockIdx.y * BM;
    const int colBase = blockIdx.x * BN;

    const __nv_bfloat16* Ap = g_mdescH + (size_t)(2 * p) * NPTS * DIM;
    const __nv_bfloat16* Bp = g_mdescH + (size_t)(2 * p + 1) * NPTS * DIM;

    float acc[4][4][4];
    #pragma unroll
    for (int mi = 0; mi < 4; mi++)
        #pragma unroll
        for (int ni = 0; ni < 4; ni++)
            #pragma unroll
            for (int e = 0; e < 4; e++) acc[mi][ni][e] = 0.f;

    const int r_ld[2]  = { tid >> 2, (tid + 256) >> 2 };
    const int c4_ld[2] = { tid & 3,  (tid + 256) & 3 };

    if (tid < BM) sRow[tid] = 0.f;
    else sCol[tid - BM] = 0.f;

    uint4 pa[2], pb[2];
    #pragma unroll
    for (int i = 0; i < 2; i++) {
        pa[i] = *(const uint4*)(Ap + (size_t)(rowBase + r_ld[i]) * DIM + c4_ld[i] * 8);
        pb[i] = *(const uint4*)(Bp + (size_t)(colBase + r_ld[i]) * DIM + c4_ld[i] * 8);
    }
    #pragma unroll
    for (int i = 0; i < 2; i++) {
        *(uint4*)&sA[0][r_ld[i]][c4_ld[i] * 4] = pa[i];
        *(uint4*)&sB[0][r_ld[i]][c4_ld[i] * 4] = pb[i];
    }
    __syncthreads();

    const int NKB = DIM / BKH;  // 8
    for (int kb = 0; kb < NKB; kb++) {
        const int cur = kb & 1;
        if (kb + 1 < NKB) {
            #pragma unroll
            for (int i = 0; i < 2; i++) {
                pa[i] = *(const uint4*)(Ap + (size_t)(rowBase + r_ld[i]) * DIM + (kb + 1) * BKH + c4_ld[i] * 8);
                pb[i] = *(const uint4*)(Bp + (size_t)(colBase + r_ld[i]) * DIM + (kb + 1) * BKH + c4_ld[i] * 8);
            }
        }

        #pragma unroll
        for (int ks = 0; ks < 2; ks++) {
            const int j0 = ks * 8;
            unsigned a[4][4], b[4][2];
            #pragma unroll
            for (int mi = 0; mi < 4; mi++) {
                int r0 = wm * 64 + mi * 16 + g;
                a[mi][0] = sA[cur][r0][j0 + t];
                a[mi][1] = sA[cur][r0 + 8][j0 + t];
                a[mi][2] = sA[cur][r0][j0 + t + 4];
                a[mi][3] = sA[cur][r0 + 8][j0 + t + 4];
            }
            #pragma unroll
            for (int ni = 0; ni < 4; ni++) {
                int c0 = wn * 32 + ni * 8 + g;
                b[ni][0] = sB[cur][c0][j0 + t];
                b[ni][1] = sB[cur][c0][j0 + t + 4];
            }
            #pragma unroll
            for (int mi = 0; mi < 4; mi++)
                #pragma unroll
                for (int ni = 0; ni < 4; ni++)
                    mma_bf16(acc[mi][ni], a[mi], b[ni]);
        }

        if (kb + 1 < NKB) {
            const int nxt = (kb + 1) & 1;
            #pragma unroll
            for (int i = 0; i < 2; i++) {
                *(uint4*)&sA[nxt][r_ld[i]][c4_ld[i] * 4] = pa[i];
                *(uint4*)&sB[nxt][r_ld[i]][c4_ld[i] * 4] = pb[i];
            }
            __syncthreads();
        }
    }

    // Epilogue: mask -> bf16 store + exp-sum accumulation.
    const int* m0 = mask + (size_t)(2 * p) * NPTS;
    const int* m1 = mask + (size_t)(2 * p + 1) * NPTS;
    __nv_bfloat16* Sp = g_Sh + (size_t)p * NPTS * NPTS;

    float rowP[4][2];
    float colP[4][2];
    #pragma unroll
    for (int i = 0; i < 4; i++) { rowP[i][0] = rowP[i][1] = 0.f; colP[i][0] = colP[i][1] = 0.f; }

    #pragma unroll
    for (int mi = 0; mi < 4; mi++) {
        int rm[2];
        rm[0] = m0[rowBase + wm * 64 + mi * 16 + g];
        rm[1] = m0[rowBase + wm * 64 + mi * 16 + g + 8];
        #pragma unroll
        for (int ni = 0; ni < 4; ni++) {
            int col = colBase + wn * 32 + ni * 8 + 2 * t;
            int cm0 = m1[col], cm1 = m1[col + 1];
            #pragma unroll
            for (int eh = 0; eh < 2; eh++) {
                int row = rowBase + wm * 64 + mi * 16 + g + eh * 8;
                float vx = (rm[eh] && cm0) ? acc[mi][ni][eh * 2 + 0] : -FLT_MAX;
                float vy = (rm[eh] && cm1) ? acc[mi][ni][eh * 2 + 1] : -FLT_MAX;
                *(unsigned*)&Sp[(size_t)row * NPTS + col] = pack_bf16(vx, vy);
                float e0 = __expf(vx);   // exp(-FLT_MAX) == 0
                float e1 = __expf(vy);
                rowP[mi][eh] += e0 + e1;
                colP[ni][0] += e0;
                colP[ni][1] += e1;
            }
        }
    }

    __syncthreads();

    #pragma unroll
    for (int mi = 0; mi < 4; mi++)
        #pragma unroll
        for (int eh = 0; eh < 2; eh++) {
            float r = rowP[mi][eh];
            r += __shfl_xor_sync(0xffffffffu, r, 1);
            r += __shfl_xor_sync(0xffffffffu, r, 2);
            if (t == 0) atomicAdd(&sRow[wm * 64 + mi * 16 + g + eh * 8], r);
        }
    #pragma unroll
    for (int ni = 0; ni < 4; ni++)
        #pragma unroll
        for (int c = 0; c < 2; c++) {
            float v = colP[ni][c];
            v += __shfl_xor_sync(0xffffffffu, v, 4);
            v += __shfl_xor_sync(0xffffffffu, v, 8);
            v += __shfl_xor_sync(0xffffffffu, v, 16);
            if (g == 0) atomicAdd(&sCol[wn * 32 + ni * 8 + 2 * t + c], v);
        }
    __syncthreads();

    if (tid < BM) atomicAdd(&g_rowS[p * NPTS + rowBase + tid], sRow[tid]);
    else          atomicAdd(&g_colS[p * NPTS + colBase + (tid - BM)], sCol[tid - BM]);
}

// ---------------- K_match: matchability + logsigmoids + accumulator zeroing ----------------
__global__ __launch_bounds__(256) void match_kernel(const float* __restrict__ desc,
                                                    const float* __restrict__ mw,
                                                    const float* __restrict__ mb) {
    // fold init: first 16384 threads zero the exp-sum accumulators (runs before sim)
    int gid = blockIdx.x * 256 + threadIdx.x;
    if (gid < PAIRS * NPTS) { g_rowS[gid] = 0.f; g_colS[gid] = 0.f; }

    int warp = blockIdx.x * 8 + (threadIdx.x >> 5);
    int lane = threadIdx.x & 31;
    const float* dp = desc + (size_t)warp * DIM;
    float acc = 0.f;
    #pragma unroll
    for (int i = 0; i < 8; i++)
        acc = fmaf(dp[lane + 32 * i], mw[lane + 32 * i], acc);
    acc = warpSum(acc);
    if (lane == 0) {
        float m = acc + mb[0];
        g_lsP[warp] = logsigmoidf(m);
        g_lsN[warp] = logsigmoidf(-m);
    }
}

// ---------------- K3: finish rr/cc ----------------
__global__ __launch_bounds__(256) void finish_kernel(const int* __restrict__ mask) {
    int idx = blockIdx.x * 256 + threadIdx.x;
    if (idx >= PAIRS * NPTS) return;
    int p = idx >> 11, i = idx & (NPTS - 1);

    int a0 = mask[(size_t)(2 * p) * NPTS + i];
    float l0 = a0 ? __logf(g_rowS[idx]) : __logf((float)NPTS);
    g_rr[idx] = make_float2(a0 ? 1.f : 0.f, g_lsP[(size_t)(2 * p) * NPTS + i] - l0);

    int a1 = mask[(size_t)(2 * p + 1) * NPTS + i];
    float l1 = a1 ? __logf(g_colS[idx]) : __logf((float)NPTS);
    g_cc[idx] = make_float2(a1 ? 1.f : 0.f, g_lsP[(size_t)(2 * p + 1) * NPTS + i] - l1);
}

// ---------------- K5: final assembly (8 rows/block, smem cc, streaming out stores) ----------------
#define NOUT (NPTS + 1)
#define RPB 8
__global__ __launch_bounds__(256) void final_kernel(float* __restrict__ out) {
    __shared__ float2 scc[NPTS];   // 16 KB

    const int p = blockIdx.y;
    const int r0 = blockIdx.x * RPB;
    const int tid = threadIdx.x;

    // cache cc for this pair
    const float2* cc = g_cc + p * NPTS;
    #pragma unroll
    for (int i = 0; i < NPTS / 256; i++) scc[tid + 256 * i] = cc[tid + 256 * i];
    __syncthreads();

    for (int r = 0; r < RPB; r++) {
        const int n = r0 + r;
        const float2 rr = g_rr[p * NPTS + n];
        const __nv_bfloat16* Srow = g_Sh + ((size_t)p * NPTS + n) * NPTS;
        const float lsN0n = g_lsN[(size_t)(2 * p) * NPTS + n];

        const size_t base = ((size_t)p * NOUT + n) * NOUT;
        const int sh = (int)((4 - (base & 3)) & 3);
        const int K = (NOUT - sh) >> 2;
        const int rem = (NOUT - sh) & 3;

        for (int k = tid; k < K; k += 256) {
            int m0 = sh + 4 * k;
            float4 o;
            float* oc = &o.x;
            #pragma unroll
            for (int c = 0; c < 4; c++) {
                int m = m0 + c;
                if (m < NPTS) {
                    float s = __bfloat162float(__ldg(Srow + m));
                    if (s < -1e38f) s = -FLT_MAX;
                    float2 cm = scc[m];
                    oc[c] = fmaf(rr.x + cm.x, s, rr.y + cm.y);
                } else {
                    oc[c] = lsN0n;
                }
            }
            __stcs((float4*)(out + base + m0), o);
        }

        if (tid < sh) {
            int m = tid;
            float s = __bfloat162float(__ldg(Srow + m));
            if (s < -1e38f) s = -FLT_MAX;
            float2 cm = scc[m];
            __stcs(out + base + m, fmaf(rr.x + cm.x, s, rr.y + cm.y));
        } else if (tid >= 4 && tid < 4 + rem) {
            int m = sh + 4 * K + (tid - 4);
            float v;
            if (m < NPTS) {
                float s = __bfloat162float(__ldg(Srow + m));
                if (s < -1e38f) s = -FLT_MAX;
                float2 cm = scc[m];
                v = fmaf(rr.x + cm.x, s, rr.y + cm.y);
            } else {
                v = lsN0n;
            }
            __stcs(out + base + m, v);
        }
    }
}

__global__ __launch_bounds__(256) void border_kernel(float* __restrict__ out) {
    int m = blockIdx.x * 256 + threadIdx.x;
    int p = blockIdx.y;
    if (m >= NOUT) return;
    float v = (m < NPTS) ? g_lsN[(size_t)(2 * p + 1) * NPTS + m] : 0.f;
    __stcs(out + ((size_t)p * NOUT + NPTS) * NOUT + m, v);
}

// ---------------- launch ----------------
extern "C" void kernel_launch(void* const* d_in, const int* in_sizes, int n_in,
                              void* d_out, int out_size) {
    const float* descriptors = (const float*)d_in[0];
    const int*   mask        = (const int*)d_in[1];
    const float* proj_w      = (const float*)d_in[2];
    const float* proj_b      = (const float*)d_in[3];
    const float* match_w     = (const float*)d_in[4];
    const float* match_b     = (const float*)d_in[5];
    float* out = (float*)d_out;

    proj_gemm<<<dim3(DIM / BN, (BATCH * NPTS) / BM, 1), 256>>>(descriptors, proj_w, proj_b);
    match_kernel<<<(BATCH * NPTS) / 8, 256>>>(descriptors, match_w, match_b);
    sim_gemm<<<dim3(NPTS / BN, NPTS / BM, PAIRS), 256>>>(mask);
    finish_kernel<<<(PAIRS * NPTS + 255) / 256, 256>>>(mask);
    final_kernel<<<dim3(NPTS / RPB, PAIRS), 256>>>(out);
    border_kernel<<<dim3((NOUT + 255) / 256, PAIRS), 256>>>(out);
}

// round 11
// speedup vs baseline: 1.4783x; 1.0165x over previous
#include <cuda_runtime.h>
#include <cuda_bf16.h>
#include <math.h>
#include <float.h>
#include <stdint.h>

// Problem constants
#define BATCH 16
#define PAIRS 8
#define NPTS  2048
#define DIM   256

// GEMM tiling
#define BM 128
#define BN 128
#define BKH 32          // bf16 elements per k-block
#define SW 20           // smem row stride in uint32 (16 data + 4 pad) -> conflict-free

#define LOG_N 7.6246189861593985f   // log(2048)

// ---------------- device scratch ----------------
__device__ __nv_bfloat16 g_mdescH[(size_t)BATCH * NPTS * DIM];    // 16.8 MB
__device__ __nv_bfloat16 g_Sh[(size_t)PAIRS * NPTS * NPTS];       // 67 MB (bf16 S)
__device__ float  g_lsP[BATCH * NPTS];
__device__ float  g_lsN[BATCH * NPTS];
__device__ float  g_rowS[PAIRS * NPTS];
__device__ float  g_colS[PAIRS * NPTS];

// ---------------- helpers ----------------
__device__ __forceinline__ unsigned pack_bf16(float lo, float hi) {
    unsigned r;
    asm("cvt.rn.bf16x2.f32 %0, %1, %2;" : "=r"(r) : "f"(hi), "f"(lo));
    return r;
}

__device__ __forceinline__ void mma_bf16(float c[4], const unsigned a[4], const unsigned b[2]) {
    asm volatile(
        "mma.sync.aligned.m16n8k16.row.col.f32.bf16.bf16.f32 "
        "{%0,%1,%2,%3},{%4,%5,%6,%7},{%8,%9},{%0,%1,%2,%3};"
        : "+f"(c[0]), "+f"(c[1]), "+f"(c[2]), "+f"(c[3])
        : "r"(a[0]), "r"(a[1]), "r"(a[2]), "r"(a[3]), "r"(b[0]), "r"(b[1]));
}

__device__ __forceinline__ float logsigmoidf(float x) {
    return fminf(x, 0.f) - log1pf(expf(-fabsf(x)));
}

__device__ __forceinline__ float warpSum(float v) {
    #pragma unroll
    for (int o = 16; o > 0; o >>= 1) v += __shfl_xor_sync(0xffffffffu, v, o);
    return v;
}

// ---------------- K1: projection GEMM (fp32 in -> bf16 mma -> bf16 out) ----------------
__global__ __launch_bounds__(256) void proj_gemm(const float* __restrict__ A,
                                                 const float* __restrict__ W,
                                                 const float* __restrict__ bias) {
    __shared__ unsigned sA[BM][SW];
    __shared__ unsigned sB[BN][SW];

    const int tid = threadIdx.x;
    const int wid = tid >> 5, lane = tid & 31;
    const int wm = wid >> 2, wn = wid & 3;
    const int g = lane >> 2, t = lane & 3;

    const int rowBase = blockIdx.y * BM;
    const int colBase = blockIdx.x * BN;

    float acc[4][4][4];
    #pragma unroll
    for (int mi = 0; mi < 4; mi++)
        #pragma unroll
        for (int ni = 0; ni < 4; ni++)
            #pragma unroll
            for (int e = 0; e < 4; e++) acc[mi][ni][e] = 0.f;

    for (int kb = 0; kb < DIM; kb += BKH) {
        #pragma unroll
        for (int i = 0; i < 4; i++) {
            int idx = tid + i * 256;
            int r = idx >> 3;
            int c4 = idx & 7;
            float4 va = *(const float4*)(A + (size_t)(rowBase + r) * DIM + kb + c4 * 4);
            sA[r][c4 * 2 + 0] = pack_bf16(va.x, va.y);
            sA[r][c4 * 2 + 1] = pack_bf16(va.z, va.w);
            float4 vb = *(const float4*)(W + (size_t)(colBase + r) * DIM + kb + c4 * 4);
            sB[r][c4 * 2 + 0] = pack_bf16(vb.x, vb.y);
            sB[r][c4 * 2 + 1] = pack_bf16(vb.z, vb.w);
        }
        __syncthreads();

        #pragma unroll
        for (int ks = 0; ks < 2; ks++) {
            const int j0 = ks * 8;
            unsigned a[4][4], b[4][2];
            #pragma unroll
            for (int mi = 0; mi < 4; mi++) {
                int r0 = wm * 64 + mi * 16 + g;
                a[mi][0] = sA[r0][j0 + t];
                a[mi][1] = sA[r0 + 8][j0 + t];
                a[mi][2] = sA[r0][j0 + t + 4];
                a[mi][3] = sA[r0 + 8][j0 + t + 4];
            }
            #pragma unroll
            for (int ni = 0; ni < 4; ni++) {
                int c0 = wn * 32 + ni * 8 + g;
                b[ni][0] = sB[c0][j0 + t];
                b[ni][1] = sB[c0][j0 + t + 4];
            }
            #pragma unroll
            for (int mi = 0; mi < 4; mi++)
                #pragma unroll
                for (int ni = 0; ni < 4; ni++)
                    mma_bf16(acc[mi][ni], a[mi], b[ni]);
        }
        __syncthreads();
    }

    #pragma unroll
    for (int mi = 0; mi < 4; mi++) {
        #pragma unroll
        for (int ni = 0; ni < 4; ni++) {
            #pragma unroll
            for (int eh = 0; eh < 2; eh++) {
                int row = rowBase + wm * 64 + mi * 16 + g + eh * 8;
                int col = colBase + wn * 32 + ni * 8 + 2 * t;
                float v0 = (acc[mi][ni][eh * 2 + 0] + bias[col])     * 0.25f;
                float v1 = (acc[mi][ni][eh * 2 + 1] + bias[col + 1]) * 0.25f;
                *(unsigned*)&g_mdescH[(size_t)row * DIM + col] = pack_bf16(v0, v1);
            }
        }
    }
}

// ---------------- K2: similarity GEMM + fused mask/exp-sum epilogue (R5 verbatim) ----------------
__global__ __launch_bounds__(256) void sim_gemm(const int* __restrict__ mask) {
    __shared__ unsigned sA[2][BM][SW];
    __shared__ unsigned sB[2][BN][SW];
    __shared__ float sRow[BM];
    __shared__ float sCol[BN];

    const int tid = threadIdx.x;
    const int wid = tid >> 5, lane = tid & 31;
    const int wm = wid >> 2, wn = wid & 3;
    const int g = lane >> 2, t = lane & 3;

    const int p = blockIdx.z;
    const int rowBase = blockIdx.y * BM;
    const int colBase = blockIdx.x * BN;

    const __nv_bfloat16* Ap = g_mdescH + (size_t)(2 * p) * NPTS * DIM;
    const __nv_bfloat16* Bp = g_mdescH + (size_t)(2 * p + 1) * NPTS * DIM;

    float acc[4][4][4];
    #pragma unroll
    for (int mi = 0; mi < 4; mi++)
        #pragma unroll
        for (int ni = 0; ni < 4; ni++)
            #pragma unroll
            for (int e = 0; e < 4; e++) acc[mi][ni][e] = 0.f;

    const int r_ld[2]  = { tid >> 2, (tid + 256) >> 2 };
    const int c4_ld[2] = { tid & 3,  (tid + 256) & 3 };

    if (tid < BM) sRow[tid] = 0.f;
    else sCol[tid - BM] = 0.f;

    uint4 pa[2], pb[2];
    #pragma unroll
    for (int i = 0; i < 2; i++) {
        pa[i] = *(const uint4*)(Ap + (size_t)(rowBase + r_ld[i]) * DIM + c4_ld[i] * 8);
        pb[i] = *(const uint4*)(Bp + (size_t)(colBase + r_ld[i]) * DIM + c4_ld[i] * 8);
    }
    #pragma unroll
    for (int i = 0; i < 2; i++) {
        *(uint4*)&sA[0][r_ld[i]][c4_ld[i] * 4] = pa[i];
        *(uint4*)&sB[0][r_ld[i]][c4_ld[i] * 4] = pb[i];
    }
    __syncthreads();

    const int NKB = DIM / BKH;  // 8
    for (int kb = 0; kb < NKB; kb++) {
        const int cur = kb & 1;
        if (kb + 1 < NKB) {
            #pragma unroll
            for (int i = 0; i < 2; i++) {
                pa[i] = *(const uint4*)(Ap + (size_t)(rowBase + r_ld[i]) * DIM + (kb + 1) * BKH + c4_ld[i] * 8);
                pb[i] = *(const uint4*)(Bp + (size_t)(colBase + r_ld[i]) * DIM + (kb + 1) * BKH + c4_ld[i] * 8);
            }
        }

        #pragma unroll
        for (int ks = 0; ks < 2; ks++) {
            const int j0 = ks * 8;
            unsigned a[4][4], b[4][2];
            #pragma unroll
            for (int mi = 0; mi < 4; mi++) {
                int r0 = wm * 64 + mi * 16 + g;
                a[mi][0] = sA[cur][r0][j0 + t];
                a[mi][1] = sA[cur][r0 + 8][j0 + t];
                a[mi][2] = sA[cur][r0][j0 + t + 4];
                a[mi][3] = sA[cur][r0 + 8][j0 + t + 4];
            }
            #pragma unroll
            for (int ni = 0; ni < 4; ni++) {
                int c0 = wn * 32 + ni * 8 + g;
                b[ni][0] = sB[cur][c0][j0 + t];
                b[ni][1] = sB[cur][c0][j0 + t + 4];
            }
            #pragma unroll
            for (int mi = 0; mi < 4; mi++)
                #pragma unroll
                for (int ni = 0; ni < 4; ni++)
                    mma_bf16(acc[mi][ni], a[mi], b[ni]);
        }

        if (kb + 1 < NKB) {
            const int nxt = (kb + 1) & 1;
            #pragma unroll
            for (int i = 0; i < 2; i++) {
                *(uint4*)&sA[nxt][r_ld[i]][c4_ld[i] * 4] = pa[i];
                *(uint4*)&sB[nxt][r_ld[i]][c4_ld[i] * 4] = pb[i];
            }
            __syncthreads();
        }
    }

    // Epilogue: mask -> bf16 store + exp-sum accumulation.
    const int* m0 = mask + (size_t)(2 * p) * NPTS;
    const int* m1 = mask + (size_t)(2 * p + 1) * NPTS;
    __nv_bfloat16* Sp = g_Sh + (size_t)p * NPTS * NPTS;

    float rowP[4][2];
    float colP[4][2];
    #pragma unroll
    for (int i = 0; i < 4; i++) { rowP[i][0] = rowP[i][1] = 0.f; colP[i][0] = colP[i][1] = 0.f; }

    #pragma unroll
    for (int mi = 0; mi < 4; mi++) {
        int rm[2];
        rm[0] = m0[rowBase + wm * 64 + mi * 16 + g];
        rm[1] = m0[rowBase + wm * 64 + mi * 16 + g + 8];
        #pragma unroll
        for (int ni = 0; ni < 4; ni++) {
            int col = colBase + wn * 32 + ni * 8 + 2 * t;
            int cm0 = m1[col], cm1 = m1[col + 1];
            #pragma unroll
            for (int eh = 0; eh < 2; eh++) {
                int row = rowBase + wm * 64 + mi * 16 + g + eh * 8;
                float vx = (rm[eh] && cm0) ? acc[mi][ni][eh * 2 + 0] : -FLT_MAX;
                float vy = (rm[eh] && cm1) ? acc[mi][ni][eh * 2 + 1] : -FLT_MAX;
                *(unsigned*)&Sp[(size_t)row * NPTS + col] = pack_bf16(vx, vy);
                float e0 = __expf(vx);   // exp(-FLT_MAX) == 0
                float e1 = __expf(vy);
                rowP[mi][eh] += e0 + e1;
                colP[ni][0] += e0;
                colP[ni][1] += e1;
            }
        }
    }

    __syncthreads();

    #pragma unroll
    for (int mi = 0; mi < 4; mi++)
        #pragma unroll
        for (int eh = 0; eh < 2; eh++) {
            float r = rowP[mi][eh];
            r += __shfl_xor_sync(0xffffffffu, r, 1);
            r += __shfl_xor_sync(0xffffffffu, r, 2);
            if (t == 0) atomicAdd(&sRow[wm * 64 + mi * 16 + g + eh * 8], r);
        }
    #pragma unroll
    for (int ni = 0; ni < 4; ni++)
        #pragma unroll
        for (int c = 0; c < 2; c++) {
            float v = colP[ni][c];
            v += __shfl_xor_sync(0xffffffffu, v, 4);
            v += __shfl_xor_sync(0xffffffffu, v, 8);
            v += __shfl_xor_sync(0xffffffffu, v, 16);
            if (g == 0) atomicAdd(&sCol[wn * 32 + ni * 8 + 2 * t + c], v);
        }
    __syncthreads();

    if (tid < BM) atomicAdd(&g_rowS[p * NPTS + rowBase + tid], sRow[tid]);
    else          atomicAdd(&g_colS[p * NPTS + colBase + (tid - BM)], sCol[tid - BM]);
}

// ---------------- K_match: matchability + logsigmoids + accumulator zeroing ----------------
__global__ __launch_bounds__(256) void match_kernel(const float* __restrict__ desc,
                                                    const float* __restrict__ mw,
                                                    const float* __restrict__ mb) {
    // fold init: first 16384 threads zero the exp-sum accumulators (runs before sim)
    int gid = blockIdx.x * 256 + threadIdx.x;
    if (gid < PAIRS * NPTS) { g_rowS[gid] = 0.f; g_colS[gid] = 0.f; }

    int warp = blockIdx.x * 8 + (threadIdx.x >> 5);
    int lane = threadIdx.x & 31;
    const float* dp = desc + (size_t)warp * DIM;
    float acc = 0.f;
    #pragma unroll
    for (int i = 0; i < 8; i++)
        acc = fmaf(dp[lane + 32 * i], mw[lane + 32 * i], acc);
    acc = warpSum(acc);
    if (lane == 0) {
        float m = acc + mb[0];
        g_lsP[warp] = logsigmoidf(m);
        g_lsN[warp] = logsigmoidf(-m);
    }
}

// ---------------- K5: final assembly (fused finish + border) ----------------
#define NOUT (NPTS + 1)
#define RPB 8
__global__ __launch_bounds__(256) void final_kernel(const int* __restrict__ mask,
                                                    float* __restrict__ out) {
    const int p = blockIdx.y;
    const int tid = threadIdx.x;

    // border slice: row n == NPTS
    if (blockIdx.x == NPTS / RPB) {
        const float* lsN1 = g_lsN + (size_t)(2 * p + 1) * NPTS;
        const size_t base = ((size_t)p * NOUT + NPTS) * NOUT;
        for (int m = tid; m < NOUT; m += 256) {
            float v = (m < NPTS) ? lsN1[m] : 0.f;
            __stcs(out + base + m, v);
        }
        return;
    }

    __shared__ float2 scc[NPTS];   // (colActive, lsP1 - colLse), 16 KB
    __shared__ float2 srr[RPB];    // (rowActive, lsP0 - rowLse)
    __shared__ float  slsN0[RPB];

    const int r0 = blockIdx.x * RPB;
    const int* m1 = mask + (size_t)(2 * p + 1) * NPTS;
    const float* lsP1 = g_lsP + (size_t)(2 * p + 1) * NPTS;

    // build cc from raw column sums
    #pragma unroll
    for (int i = 0; i < NPTS / 256; i++) {
        int m = tid + 256 * i;
        int a1 = m1[m];
        float lse = a1 ? __logf(g_colS[p * NPTS + m]) : LOG_N;
        scc[m] = make_float2(a1 ? 1.f : 0.f, lsP1[m] - lse);
    }
    // build rr for this block's rows
    if (tid < RPB) {
        int n = r0 + tid;
        int a0 = mask[(size_t)(2 * p) * NPTS + n];
        float lse = a0 ? __logf(g_rowS[p * NPTS + n]) : LOG_N;
        srr[tid] = make_float2(a0 ? 1.f : 0.f, g_lsP[(size_t)(2 * p) * NPTS + n] - lse);
        slsN0[tid] = g_lsN[(size_t)(2 * p) * NPTS + n];
    }
    __syncthreads();

    for (int r = 0; r < RPB; r++) {
        const int n = r0 + r;
        const float2 rr = srr[r];
        const __nv_bfloat16* Srow = g_Sh + ((size_t)p * NPTS + n) * NPTS;
        const float lsN0n = slsN0[r];

        const size_t base = ((size_t)p * NOUT + n) * NOUT;
        const int sh = (int)((4 - (base & 3)) & 3);
        const int K = (NOUT - sh) >> 2;
        const int rem = (NOUT - sh) & 3;

        for (int k = tid; k < K; k += 256) {
            int m0 = sh + 4 * k;
            float4 o;
            float* oc = &o.x;
            #pragma unroll
            for (int c = 0; c < 4; c++) {
                int m = m0 + c;
                if (m < NPTS) {
                    float s = __bfloat162float(__ldg(Srow + m));
                    if (s < -1e38f) s = -FLT_MAX;
                    float2 cm = scc[m];
                    oc[c] = fmaf(rr.x + cm.x, s, rr.y + cm.y);
                } else {
                    oc[c] = lsN0n;
                }
            }
            __stcs((float4*)(out + base + m0), o);
        }

        if (tid < sh) {
            int m = tid;
            float s = __bfloat162float(__ldg(Srow + m));
            if (s < -1e38f) s = -FLT_MAX;
            float2 cm = scc[m];
            __stcs(out + base + m, fmaf(rr.x + cm.x, s, rr.y + cm.y));
        } else if (tid >= 4 && tid < 4 + rem) {
            int m = sh + 4 * K + (tid - 4);
            float v;
            if (m < NPTS) {
                float s = __bfloat162float(__ldg(Srow + m));
                if (s < -1e38f) s = -FLT_MAX;
                float2 cm = scc[m];
                v = fmaf(rr.x + cm.x, s, rr.y + cm.y);
            } else {
                v = lsN0n;
            }
            __stcs(out + base + m, v);
        }
    }
}

// ---------------- launch ----------------
extern "C" void kernel_launch(void* const* d_in, const int* in_sizes, int n_in,
                              void* d_out, int out_size) {
    const float* descriptors = (const float*)d_in[0];
    const int*   mask        = (const int*)d_in[1];
    const float* proj_w      = (const float*)d_in[2];
    const float* proj_b      = (const float*)d_in[3];
    const float* match_w     = (const float*)d_in[4];
    const float* match_b     = (const float*)d_in[5];
    float* out = (float*)d_out;

    proj_gemm<<<dim3(DIM / BN, (BATCH * NPTS) / BM, 1), 256>>>(descriptors, proj_w, proj_b);
    match_kernel<<<(BATCH * NPTS) / 8, 256>>>(descriptors, match_w, match_b);
    sim_gemm<<<dim3(NPTS / BN, NPTS / BM, PAIRS), 256>>>(mask);
    final_kernel<<<dim3(NPTS / RPB + 1, PAIRS), 256>>>(mask, out);
}

// round 12
// speedup vs baseline: 1.6252x; 1.0994x over previous
#include <cuda_runtime.h>
#include <cuda_bf16.h>
#include <math.h>
#include <float.h>
#include <stdint.h>

// Problem constants
#define BATCH 16
#define PAIRS 8
#define NPTS  2048
#define DIM   256

// GEMM tiling
#define BM 128
#define BN 128
#define BKH 32          // bf16 elements per k-block
#define SW 20           // smem row stride in uint32 (16 data + 4 pad) -> conflict-free

#define LOG_N 7.6246189861593985f   // log(2048)

// ---------------- device scratch ----------------
__device__ __nv_bfloat16 g_mdescH[(size_t)BATCH * NPTS * DIM];    // 16.8 MB
__device__ __nv_bfloat16 g_Sh[(size_t)PAIRS * NPTS * NPTS];       // 67 MB (bf16 S)
__device__ float  g_lsP[BATCH * NPTS];
__device__ float  g_lsN[BATCH * NPTS];
__device__ float  g_rowS[PAIRS * NPTS];
__device__ float  g_colS[PAIRS * NPTS];

// ---------------- helpers ----------------
__device__ __forceinline__ unsigned pack_bf16(float lo, float hi) {
    unsigned r;
    asm("cvt.rn.bf16x2.f32 %0, %1, %2;" : "=r"(r) : "f"(hi), "f"(lo));
    return r;
}

__device__ __forceinline__ void mma_bf16(float c[4], const unsigned a[4], const unsigned b[2]) {
    asm volatile(
        "mma.sync.aligned.m16n8k16.row.col.f32.bf16.bf16.f32 "
        "{%0,%1,%2,%3},{%4,%5,%6,%7},{%8,%9},{%0,%1,%2,%3};"
        : "+f"(c[0]), "+f"(c[1]), "+f"(c[2]), "+f"(c[3])
        : "r"(a[0]), "r"(a[1]), "r"(a[2]), "r"(a[3]), "r"(b[0]), "r"(b[1]));
}

__device__ __forceinline__ float logsigmoidf(float x) {
    return fminf(x, 0.f) - log1pf(expf(-fabsf(x)));
}

__device__ __forceinline__ float warpSum(float v) {
    #pragma unroll
    for (int o = 16; o > 0; o >>= 1) v += __shfl_xor_sync(0xffffffffu, v, o);
    return v;
}

// ---------------- K1: projection GEMM (fp32 in -> bf16 mma -> bf16 out) ----------------
__global__ __launch_bounds__(256) void proj_gemm(const float* __restrict__ A,
                                                 const float* __restrict__ W,
                                                 const float* __restrict__ bias) {
    __shared__ unsigned sA[BM][SW];
    __shared__ unsigned sB[BN][SW];

    const int tid = threadIdx.x;
    const int wid = tid >> 5, lane = tid & 31;
    const int wm = wid >> 2, wn = wid & 3;
    const int g = lane >> 2, t = lane & 3;

    const int rowBase = blockIdx.y * BM;
    const int colBase = blockIdx.x * BN;

    float acc[4][4][4];
    #pragma unroll
    for (int mi = 0; mi < 4; mi++)
        #pragma unroll
        for (int ni = 0; ni < 4; ni++)
            #pragma unroll
            for (int e = 0; e < 4; e++) acc[mi][ni][e] = 0.f;

    for (int kb = 0; kb < DIM; kb += BKH) {
        #pragma unroll
        for (int i = 0; i < 4; i++) {
            int idx = tid + i * 256;
            int r = idx >> 3;
            int c4 = idx & 7;
            float4 va = *(const float4*)(A + (size_t)(rowBase + r) * DIM + kb + c4 * 4);
            sA[r][c4 * 2 + 0] = pack_bf16(va.x, va.y);
            sA[r][c4 * 2 + 1] = pack_bf16(va.z, va.w);
            float4 vb = *(const float4*)(W + (size_t)(colBase + r) * DIM + kb + c4 * 4);
            sB[r][c4 * 2 + 0] = pack_bf16(vb.x, vb.y);
            sB[r][c4 * 2 + 1] = pack_bf16(vb.z, vb.w);
        }
        __syncthreads();

        #pragma unroll
        for (int ks = 0; ks < 2; ks++) {
            const int j0 = ks * 8;
            unsigned a[4][4], b[4][2];
            #pragma unroll
            for (int mi = 0; mi < 4; mi++) {
                int r0 = wm * 64 + mi * 16 + g;
                a[mi][0] = sA[r0][j0 + t];
                a[mi][1] = sA[r0 + 8][j0 + t];
                a[mi][2] = sA[r0][j0 + t + 4];
                a[mi][3] = sA[r0 + 8][j0 + t + 4];
            }
            #pragma unroll
            for (int ni = 0; ni < 4; ni++) {
                int c0 = wn * 32 + ni * 8 + g;
                b[ni][0] = sB[c0][j0 + t];
                b[ni][1] = sB[c0][j0 + t + 4];
            }
            #pragma unroll
            for (int mi = 0; mi < 4; mi++)
                #pragma unroll
                for (int ni = 0; ni < 4; ni++)
                    mma_bf16(acc[mi][ni], a[mi], b[ni]);
        }
        __syncthreads();
    }

    #pragma unroll
    for (int mi = 0; mi < 4; mi++) {
        #pragma unroll
        for (int ni = 0; ni < 4; ni++) {
            #pragma unroll
            for (int eh = 0; eh < 2; eh++) {
                int row = rowBase + wm * 64 + mi * 16 + g + eh * 8;
                int col = colBase + wn * 32 + ni * 8 + 2 * t;
                float v0 = (acc[mi][ni][eh * 2 + 0] + bias[col])     * 0.25f;
                float v1 = (acc[mi][ni][eh * 2 + 1] + bias[col + 1]) * 0.25f;
                *(unsigned*)&g_mdescH[(size_t)row * DIM + col] = pack_bf16(v0, v1);
            }
        }
    }
}

// ---------------- K2: similarity GEMM + fused mask/exp-sum epilogue (R5 verbatim) ----------------
__global__ __launch_bounds__(256) void sim_gemm(const int* __restrict__ mask) {
    __shared__ unsigned sA[2][BM][SW];
    __shared__ unsigned sB[2][BN][SW];
    __shared__ float sRow[BM];
    __shared__ float sCol[BN];

    const int tid = threadIdx.x;
    const int wid = tid >> 5, lane = tid & 31;
    const int wm = wid >> 2, wn = wid & 3;
    const int g = lane >> 2, t = lane & 3;

    const int p = blockIdx.z;
    const int rowBase = blockIdx.y * BM;
    const int colBase = blockIdx.x * BN;

    const __nv_bfloat16* Ap = g_mdescH + (size_t)(2 * p) * NPTS * DIM;
    const __nv_bfloat16* Bp = g_mdescH + (size_t)(2 * p + 1) * NPTS * DIM;

    float acc[4][4][4];
    #pragma unroll
    for (int mi = 0; mi < 4; mi++)
        #pragma unroll
        for (int ni = 0; ni < 4; ni++)
            #pragma unroll
            for (int e = 0; e < 4; e++) acc[mi][ni][e] = 0.f;

    const int r_ld[2]  = { tid >> 2, (tid + 256) >> 2 };
    const int c4_ld[2] = { tid & 3,  (tid + 256) & 3 };

    if (tid < BM) sRow[tid] = 0.f;
    else sCol[tid - BM] = 0.f;

    uint4 pa[2], pb[2];
    #pragma unroll
    for (int i = 0; i < 2; i++) {
        pa[i] = *(const uint4*)(Ap + (size_t)(rowBase + r_ld[i]) * DIM + c4_ld[i] * 8);
        pb[i] = *(const uint4*)(Bp + (size_t)(colBase + r_ld[i]) * DIM + c4_ld[i] * 8);
    }
    #pragma unroll
    for (int i = 0; i < 2; i++) {
        *(uint4*)&sA[0][r_ld[i]][c4_ld[i] * 4] = pa[i];
        *(uint4*)&sB[0][r_ld[i]][c4_ld[i] * 4] = pb[i];
    }
    __syncthreads();

    const int NKB = DIM / BKH;  // 8
    for (int kb = 0; kb < NKB; kb++) {
        const int cur = kb & 1;
        if (kb + 1 < NKB) {
            #pragma unroll
            for (int i = 0; i < 2; i++) {
                pa[i] = *(const uint4*)(Ap + (size_t)(rowBase + r_ld[i]) * DIM + (kb + 1) * BKH + c4_ld[i] * 8);
                pb[i] = *(const uint4*)(Bp + (size_t)(colBase + r_ld[i]) * DIM + (kb + 1) * BKH + c4_ld[i] * 8);
            }
        }

        #pragma unroll
        for (int ks = 0; ks < 2; ks++) {
            const int j0 = ks * 8;
            unsigned a[4][4], b[4][2];
            #pragma unroll
            for (int mi = 0; mi < 4; mi++) {
                int r0 = wm * 64 + mi * 16 + g;
                a[mi][0] = sA[cur][r0][j0 + t];
                a[mi][1] = sA[cur][r0 + 8][j0 + t];
                a[mi][2] = sA[cur][r0][j0 + t + 4];
                a[mi][3] = sA[cur][r0 + 8][j0 + t + 4];
            }
            #pragma unroll
            for (int ni = 0; ni < 4; ni++) {
                int c0 = wn * 32 + ni * 8 + g;
                b[ni][0] = sB[cur][c0][j0 + t];
                b[ni][1] = sB[cur][c0][j0 + t + 4];
            }
            #pragma unroll
            for (int mi = 0; mi < 4; mi++)
                #pragma unroll
                for (int ni = 0; ni < 4; ni++)
                    mma_bf16(acc[mi][ni], a[mi], b[ni]);
        }

        if (kb + 1 < NKB) {
            const int nxt = (kb + 1) & 1;
            #pragma unroll
            for (int i = 0; i < 2; i++) {
                *(uint4*)&sA[nxt][r_ld[i]][c4_ld[i] * 4] = pa[i];
                *(uint4*)&sB[nxt][r_ld[i]][c4_ld[i] * 4] = pb[i];
            }
            __syncthreads();
        }
    }

    // Epilogue: mask -> bf16 store + exp-sum accumulation.
    const int* m0 = mask + (size_t)(2 * p) * NPTS;
    const int* m1 = mask + (size_t)(2 * p + 1) * NPTS;
    __nv_bfloat16* Sp = g_Sh + (size_t)p * NPTS * NPTS;

    float rowP[4][2];
    float colP[4][2];
    #pragma unroll
    for (int i = 0; i < 4; i++) { rowP[i][0] = rowP[i][1] = 0.f; colP[i][0] = colP[i][1] = 0.f; }

    #pragma unroll
    for (int mi = 0; mi < 4; mi++) {
        int rm[2];
        rm[0] = m0[rowBase + wm * 64 + mi * 16 + g];
        rm[1] = m0[rowBase + wm * 64 + mi * 16 + g + 8];
        #pragma unroll
        for (int ni = 0; ni < 4; ni++) {
            int col = colBase + wn * 32 + ni * 8 + 2 * t;
            int cm0 = m1[col], cm1 = m1[col + 1];
            #pragma unroll
            for (int eh = 0; eh < 2; eh++) {
                int row = rowBase + wm * 64 + mi * 16 + g + eh * 8;
                float vx = (rm[eh] && cm0) ? acc[mi][ni][eh * 2 + 0] : -FLT_MAX;
                float vy = (rm[eh] && cm1) ? acc[mi][ni][eh * 2 + 1] : -FLT_MAX;
                *(unsigned*)&Sp[(size_t)row * NPTS + col] = pack_bf16(vx, vy);
                float e0 = __expf(vx);   // exp(-FLT_MAX) == 0
                float e1 = __expf(vy);
                rowP[mi][eh] += e0 + e1;
                colP[ni][0] += e0;
                colP[ni][1] += e1;
            }
        }
    }

    __syncthreads();

    #pragma unroll
    for (int mi = 0; mi < 4; mi++)
        #pragma unroll
        for (int eh = 0; eh < 2; eh++) {
            float r = rowP[mi][eh];
            r += __shfl_xor_sync(0xffffffffu, r, 1);
            r += __shfl_xor_sync(0xffffffffu, r, 2);
            if (t == 0) atomicAdd(&sRow[wm * 64 + mi * 16 + g + eh * 8], r);
        }
    #pragma unroll
    for (int ni = 0; ni < 4; ni++)
        #pragma unroll
        for (int c = 0; c < 2; c++) {
            float v = colP[ni][c];
            v += __shfl_xor_sync(0xffffffffu, v, 4);
            v += __shfl_xor_sync(0xffffffffu, v, 8);
            v += __shfl_xor_sync(0xffffffffu, v, 16);
            if (g == 0) atomicAdd(&sCol[wn * 32 + ni * 8 + 2 * t + c], v);
        }
    __syncthreads();

    if (tid < BM) atomicAdd(&g_rowS[p * NPTS + rowBase + tid], sRow[tid]);
    else          atomicAdd(&g_colS[p * NPTS + colBase + (tid - BM)], sCol[tid - BM]);
}

// ---------------- K_match: matchability + logsigmoids + accumulator zeroing ----------------
__global__ __launch_bounds__(256) void match_kernel(const float* __restrict__ desc,
                                                    const float* __restrict__ mw,
                                                    const float* __restrict__ mb) {
    // fold init: first 16384 threads zero the exp-sum accumulators (runs before sim)
    int gid = blockIdx.x * 256 + threadIdx.x;
    if (gid < PAIRS * NPTS) { g_rowS[gid] = 0.f; g_colS[gid] = 0.f; }

    int warp = blockIdx.x * 8 + (threadIdx.x >> 5);
    int lane = threadIdx.x & 31;
    const float* dp = desc + (size_t)warp * DIM;
    float acc = 0.f;
    #pragma unroll
    for (int i = 0; i < 8; i++)
        acc = fmaf(dp[lane + 32 * i], mw[lane + 32 * i], acc);
    acc = warpSum(acc);
    if (lane == 0) {
        float m = acc + mb[0];
        g_lsP[warp] = logsigmoidf(m);
        g_lsN[warp] = logsigmoidf(-m);
    }
}

// ---------------- K5: final assembly (stride-256 scalar mapping, fused border) ----------------
#define NOUT (NPTS + 1)
#define RPB 8
__global__ __launch_bounds__(256) void final_kernel(const int* __restrict__ mask,
                                                    float* __restrict__ out) {
    const int p = blockIdx.y;
    const int tid = threadIdx.x;

    // border slice: row n == NPTS
    if (blockIdx.x == NPTS / RPB) {
        const float* lsN1 = g_lsN + (size_t)(2 * p + 1) * NPTS;
        const size_t base = ((size_t)p * NOUT + NPTS) * NOUT;
        for (int m = tid; m < NOUT; m += 256) {
            float v = (m < NPTS) ? lsN1[m] : 0.f;
            __stcs(out + base + m, v);
        }
        return;
    }

    __shared__ float2 scc[NPTS];   // (colActive, lsP1 - colLse), 16 KB
    __shared__ float2 srr[RPB];    // (rowActive, lsP0 - rowLse)
    __shared__ float  slsN0[RPB];

    const int r0 = blockIdx.x * RPB;
    const int* m1 = mask + (size_t)(2 * p + 1) * NPTS;
    const float* lsP1 = g_lsP + (size_t)(2 * p + 1) * NPTS;

    // build cc from raw column sums
    #pragma unroll
    for (int i = 0; i < NPTS / 256; i++) {
        int m = tid + 256 * i;
        int a1 = m1[m];
        float lse = a1 ? __logf(g_colS[p * NPTS + m]) : LOG_N;
        scc[m] = make_float2(a1 ? 1.f : 0.f, lsP1[m] - lse);
    }
    // build rr for this block's rows
    if (tid < RPB) {
        int n = r0 + tid;
        int a0 = mask[(size_t)(2 * p) * NPTS + n];
        float lse = a0 ? __logf(g_rowS[p * NPTS + n]) : LOG_N;
        srr[tid] = make_float2(a0 ? 1.f : 0.f, g_lsP[(size_t)(2 * p) * NPTS + n] - lse);
        slsN0[tid] = g_lsN[(size_t)(2 * p) * NPTS + n];
    }
    __syncthreads();

    #pragma unroll
    for (int r = 0; r < RPB; r++) {
        const int n = r0 + r;
        const float2 rr = srr[r];
        const __nv_bfloat16* Srow = g_Sh + ((size_t)p * NPTS + n) * NPTS;
        float* orow = out + ((size_t)p * NOUT + n) * NOUT;

        // stride-256 scalar mapping: conflict-free scc LDS, coalesced S loads + out stores
        #pragma unroll
        for (int i = 0; i < NPTS / 256; i++) {
            int m = tid + 256 * i;
            float s = __bfloat162float(__ldg(Srow + m));
            s = fmaxf(s, -FLT_MAX);        // masked entries: -inf -> exactly -FLT_MAX
            float2 cm = scc[m];
            __stcs(orow + m, fmaf(rr.x + cm.x, s, rr.y + cm.y));
        }
        if (tid == 0) __stcs(orow + NPTS, slsN0[r]);   // m == NPTS column
    }
}

// ---------------- launch ----------------
extern "C" void kernel_launch(void* const* d_in, const int* in_sizes, int n_in,
                              void* d_out, int out_size) {
    const float* descriptors = (const float*)d_in[0];
    const int*   mask        = (const int*)d_in[1];
    const float* proj_w      = (const float*)d_in[2];
    const float* proj_b      = (const float*)d_in[3];
    const float* match_w     = (const float*)d_in[4];
    const float* match_b     = (const float*)d_in[5];
    float* out = (float*)d_out;

    proj_gemm<<<dim3(DIM / BN, (BATCH * NPTS) / BM, 1), 256>>>(descriptors, proj_w, proj_b);
    match_kernel<<<(BATCH * NPTS) / 8, 256>>>(descriptors, match_w, match_b);
    sim_gemm<<<dim3(NPTS / BN, NPTS / BM, PAIRS), 256>>>(mask);
    final_kernel<<<dim3(NPTS / RPB + 1, PAIRS), 256>>>(mask, out);
}

// round 13
// speedup vs baseline: 1.6411x; 1.0098x over previous
#include <cuda_runtime.h>
#include <cuda_bf16.h>
#include <math.h>
#include <float.h>
#include <stdint.h>

// Problem constants
#define BATCH 16
#define PAIRS 8
#define NPTS  2048
#define DIM   256

// GEMM tiling
#define BM 128
#define BN 128
#define BKH 32          // bf16 elements per k-block
#define SW 20           // smem row stride in uint32 (16 data + 4 pad) -> conflict-free

#define LOG_N 7.6246189861593985f   // log(2048)

// ---------------- device scratch ----------------
__device__ __nv_bfloat16 g_mdescH[(size_t)BATCH * NPTS * DIM];    // 16.8 MB
__device__ __nv_bfloat16 g_Sh[(size_t)PAIRS * NPTS * NPTS];       // 67 MB (bf16 S)
__device__ float  g_lsP[BATCH * NPTS];
__device__ float  g_lsN[BATCH * NPTS];
__device__ float  g_rowS[PAIRS * NPTS];
__device__ float  g_colS[PAIRS * NPTS];

// ---------------- helpers ----------------
__device__ __forceinline__ unsigned pack_bf16(float lo, float hi) {
    unsigned r;
    asm("cvt.rn.bf16x2.f32 %0, %1, %2;" : "=r"(r) : "f"(hi), "f"(lo));
    return r;
}

__device__ __forceinline__ void mma_bf16(float c[4], const unsigned a[4], const unsigned b[2]) {
    asm volatile(
        "mma.sync.aligned.m16n8k16.row.col.f32.bf16.bf16.f32 "
        "{%0,%1,%2,%3},{%4,%5,%6,%7},{%8,%9},{%0,%1,%2,%3};"
        : "+f"(c[0]), "+f"(c[1]), "+f"(c[2]), "+f"(c[3])
        : "r"(a[0]), "r"(a[1]), "r"(a[2]), "r"(a[3]), "r"(b[0]), "r"(b[1]));
}

__device__ __forceinline__ float logsigmoidf(float x) {
    return fminf(x, 0.f) - log1pf(expf(-fabsf(x)));
}

__device__ __forceinline__ float warpSum(float v) {
    #pragma unroll
    for (int o = 16; o > 0; o >>= 1) v += __shfl_xor_sync(0xffffffffu, v, o);
    return v;
}

// ---------------- K1: projection GEMM (fp32 in -> bf16 mma -> bf16 out) ----------------
__global__ __launch_bounds__(256) void proj_gemm(const float* __restrict__ A,
                                                 const float* __restrict__ W,
                                                 const float* __restrict__ bias) {
    __shared__ unsigned sA[BM][SW];
    __shared__ unsigned sB[BN][SW];

    const int tid = threadIdx.x;
    const int wid = tid >> 5, lane = tid & 31;
    const int wm = wid >> 2, wn = wid & 3;
    const int g = lane >> 2, t = lane & 3;

    const int rowBase = blockIdx.y * BM;
    const int colBase = blockIdx.x * BN;

    float acc[4][4][4];
    #pragma unroll
    for (int mi = 0; mi < 4; mi++)
        #pragma unroll
        for (int ni = 0; ni < 4; ni++)
            #pragma unroll
            for (int e = 0; e < 4; e++) acc[mi][ni][e] = 0.f;

    for (int kb = 0; kb < DIM; kb += BKH) {
        #pragma unroll
        for (int i = 0; i < 4; i++) {
            int idx = tid + i * 256;
            int r = idx >> 3;
            int c4 = idx & 7;
            float4 va = *(const float4*)(A + (size_t)(rowBase + r) * DIM + kb + c4 * 4);
            sA[r][c4 * 2 + 0] = pack_bf16(va.x, va.y);
            sA[r][c4 * 2 + 1] = pack_bf16(va.z, va.w);
            float4 vb = *(const float4*)(W + (size_t)(colBase + r) * DIM + kb + c4 * 4);
            sB[r][c4 * 2 + 0] = pack_bf16(vb.x, vb.y);
            sB[r][c4 * 2 + 1] = pack_bf16(vb.z, vb.w);
        }
        __syncthreads();

        #pragma unroll
        for (int ks = 0; ks < 2; ks++) {
            const int j0 = ks * 8;
            unsigned a[4][4], b[4][2];
            #pragma unroll
            for (int mi = 0; mi < 4; mi++) {
                int r0 = wm * 64 + mi * 16 + g;
                a[mi][0] = sA[r0][j0 + t];
                a[mi][1] = sA[r0 + 8][j0 + t];
                a[mi][2] = sA[r0][j0 + t + 4];
                a[mi][3] = sA[r0 + 8][j0 + t + 4];
            }
            #pragma unroll
            for (int ni = 0; ni < 4; ni++) {
                int c0 = wn * 32 + ni * 8 + g;
                b[ni][0] = sB[c0][j0 + t];
                b[ni][1] = sB[c0][j0 + t + 4];
            }
            #pragma unroll
            for (int mi = 0; mi < 4; mi++)
                #pragma unroll
                for (int ni = 0; ni < 4; ni++)
                    mma_bf16(acc[mi][ni], a[mi], b[ni]);
        }
        __syncthreads();
    }

    #pragma unroll
    for (int mi = 0; mi < 4; mi++) {
        #pragma unroll
        for (int ni = 0; ni < 4; ni++) {
            #pragma unroll
            for (int eh = 0; eh < 2; eh++) {
                int row = rowBase + wm * 64 + mi * 16 + g + eh * 8;
                int col = colBase + wn * 32 + ni * 8 + 2 * t;
                float v0 = (acc[mi][ni][eh * 2 + 0] + bias[col])     * 0.25f;
                float v1 = (acc[mi][ni][eh * 2 + 1] + bias[col + 1]) * 0.25f;
                *(unsigned*)&g_mdescH[(size_t)row * DIM + col] = pack_bf16(v0, v1);
            }
        }
    }
}

// ---------------- K2: similarity GEMM + fused mask/exp-sum epilogue (R5 verbatim) ----------------
__global__ __launch_bounds__(256) void sim_gemm(const int* __restrict__ mask) {
    __shared__ unsigned sA[2][BM][SW];
    __shared__ unsigned sB[2][BN][SW];
    __shared__ float sRow[BM];
    __shared__ float sCol[BN];

    const int tid = threadIdx.x;
    const int wid = tid >> 5, lane = tid & 31;
    const int wm = wid >> 2, wn = wid & 3;
    const int g = lane >> 2, t = lane & 3;

    const int p = blockIdx.z;
    const int rowBase = blockIdx.y * BM;
    const int colBase = blockIdx.x * BN;

    const __nv_bfloat16* Ap = g_mdescH + (size_t)(2 * p) * NPTS * DIM;
    const __nv_bfloat16* Bp = g_mdescH + (size_t)(2 * p + 1) * NPTS * DIM;

    float acc[4][4][4];
    #pragma unroll
    for (int mi = 0; mi < 4; mi++)
        #pragma unroll
        for (int ni = 0; ni < 4; ni++)
            #pragma unroll
            for (int e = 0; e < 4; e++) acc[mi][ni][e] = 0.f;

    const int r_ld[2]  = { tid >> 2, (tid + 256) >> 2 };
    const int c4_ld[2] = { tid & 3,  (tid + 256) & 3 };

    if (tid < BM) sRow[tid] = 0.f;
    else sCol[tid - BM] = 0.f;

    uint4 pa[2], pb[2];
    #pragma unroll
    for (int i = 0; i < 2; i++) {
        pa[i] = *(const uint4*)(Ap + (size_t)(rowBase + r_ld[i]) * DIM + c4_ld[i] * 8);
        pb[i] = *(const uint4*)(Bp + (size_t)(colBase + r_ld[i]) * DIM + c4_ld[i] * 8);
    }
    #pragma unroll
    for (int i = 0; i < 2; i++) {
        *(uint4*)&sA[0][r_ld[i]][c4_ld[i] * 4] = pa[i];
        *(uint4*)&sB[0][r_ld[i]][c4_ld[i] * 4] = pb[i];
    }
    __syncthreads();

    const int NKB = DIM / BKH;  // 8
    for (int kb = 0; kb < NKB; kb++) {
        const int cur = kb & 1;
        if (kb + 1 < NKB) {
            #pragma unroll
            for (int i = 0; i < 2; i++) {
                pa[i] = *(const uint4*)(Ap + (size_t)(rowBase + r_ld[i]) * DIM + (kb + 1) * BKH + c4_ld[i] * 8);
                pb[i] = *(const uint4*)(Bp + (size_t)(colBase + r_ld[i]) * DIM + (kb + 1) * BKH + c4_ld[i] * 8);
            }
        }

        #pragma unroll
        for (int ks = 0; ks < 2; ks++) {
            const int j0 = ks * 8;
            unsigned a[4][4], b[4][2];
            #pragma unroll
            for (int mi = 0; mi < 4; mi++) {
                int r0 = wm * 64 + mi * 16 + g;
                a[mi][0] = sA[cur][r0][j0 + t];
                a[mi][1] = sA[cur][r0 + 8][j0 + t];
                a[mi][2] = sA[cur][r0][j0 + t + 4];
                a[mi][3] = sA[cur][r0 + 8][j0 + t + 4];
            }
            #pragma unroll
            for (int ni = 0; ni < 4; ni++) {
                int c0 = wn * 32 + ni * 8 + g;
                b[ni][0] = sB[cur][c0][j0 + t];
                b[ni][1] = sB[cur][c0][j0 + t + 4];
            }
            #pragma unroll
            for (int mi = 0; mi < 4; mi++)
                #pragma unroll
                for (int ni = 0; ni < 4; ni++)
                    mma_bf16(acc[mi][ni], a[mi], b[ni]);
        }

        if (kb + 1 < NKB) {
            const int nxt = (kb + 1) & 1;
            #pragma unroll
            for (int i = 0; i < 2; i++) {
                *(uint4*)&sA[nxt][r_ld[i]][c4_ld[i] * 4] = pa[i];
                *(uint4*)&sB[nxt][r_ld[i]][c4_ld[i] * 4] = pb[i];
            }
            __syncthreads();
        }
    }

    // Epilogue: mask -> bf16 store + exp-sum accumulation.
    const int* m0 = mask + (size_t)(2 * p) * NPTS;
    const int* m1 = mask + (size_t)(2 * p + 1) * NPTS;
    __nv_bfloat16* Sp = g_Sh + (size_t)p * NPTS * NPTS;

    float rowP[4][2];
    float colP[4][2];
    #pragma unroll
    for (int i = 0; i < 4; i++) { rowP[i][0] = rowP[i][1] = 0.f; colP[i][0] = colP[i][1] = 0.f; }

    #pragma unroll
    for (int mi = 0; mi < 4; mi++) {
        int rm[2];
        rm[0] = m0[rowBase + wm * 64 + mi * 16 + g];
        rm[1] = m0[rowBase + wm * 64 + mi * 16 + g + 8];
        #pragma unroll
        for (int ni = 0; ni < 4; ni++) {
            int col = colBase + wn * 32 + ni * 8 + 2 * t;
            int cm0 = m1[col], cm1 = m1[col + 1];
            #pragma unroll
            for (int eh = 0; eh < 2; eh++) {
                int row = rowBase + wm * 64 + mi * 16 + g + eh * 8;
                float vx = (rm[eh] && cm0) ? acc[mi][ni][eh * 2 + 0] : -FLT_MAX;
                float vy = (rm[eh] && cm1) ? acc[mi][ni][eh * 2 + 1] : -FLT_MAX;
                *(unsigned*)&Sp[(size_t)row * NPTS + col] = pack_bf16(vx, vy);
                float e0 = __expf(vx);   // exp(-FLT_MAX) == 0
                float e1 = __expf(vy);
                rowP[mi][eh] += e0 + e1;
                colP[ni][0] += e0;
                colP[ni][1] += e1;
            }
        }
    }

    __syncthreads();

    #pragma unroll
    for (int mi = 0; mi < 4; mi++)
        #pragma unroll
        for (int eh = 0; eh < 2; eh++) {
            float r = rowP[mi][eh];
            r += __shfl_xor_sync(0xffffffffu, r, 1);
            r += __shfl_xor_sync(0xffffffffu, r, 2);
            if (t == 0) atomicAdd(&sRow[wm * 64 + mi * 16 + g + eh * 8], r);
        }
    #pragma unroll
    for (int ni = 0; ni < 4; ni++)
        #pragma unroll
        for (int c = 0; c < 2; c++) {
            float v = colP[ni][c];
            v += __shfl_xor_sync(0xffffffffu, v, 4);
            v += __shfl_xor_sync(0xffffffffu, v, 8);
            v += __shfl_xor_sync(0xffffffffu, v, 16);
            if (g == 0) atomicAdd(&sCol[wn * 32 + ni * 8 + 2 * t + c], v);
        }
    __syncthreads();

    if (tid < BM) atomicAdd(&g_rowS[p * NPTS + rowBase + tid], sRow[tid]);
    else          atomicAdd(&g_colS[p * NPTS + colBase + (tid - BM)], sCol[tid - BM]);
}

// ---------------- K_match: matchability + logsigmoids + accumulator zeroing ----------------
__global__ __launch_bounds__(256) void match_kernel(const float* __restrict__ desc,
                                                    const float* __restrict__ mw,
                                                    const float* __restrict__ mb) {
    int gid = blockIdx.x * 256 + threadIdx.x;
    if (gid < PAIRS * NPTS) { g_rowS[gid] = 0.f; g_colS[gid] = 0.f; }

    int warp = blockIdx.x * 8 + (threadIdx.x >> 5);
    int lane = threadIdx.x & 31;
    const float* dp = desc + (size_t)warp * DIM;
    float acc = 0.f;
    #pragma unroll
    for (int i = 0; i < 8; i++)
        acc = fmaf(dp[lane + 32 * i], mw[lane + 32 * i], acc);
    acc = warpSum(acc);
    if (lane == 0) {
        float m = acc + mb[0];
        g_lsP[warp] = logsigmoidf(m);
        g_lsN[warp] = logsigmoidf(-m);
    }
}

// ---------------- K5: final assembly (paired bf16 loads, 64-bit stores, fused border) ----------------
#define NOUT (NPTS + 1)
#define RPB 8
__global__ __launch_bounds__(256) void final_kernel(const int* __restrict__ mask,
                                                    float* __restrict__ out) {
    const int p = blockIdx.y;
    const int tid = threadIdx.x;

    // border slice: row n == NPTS
    if (blockIdx.x == NPTS / RPB) {
        const float* lsN1 = g_lsN + (size_t)(2 * p + 1) * NPTS;
        const size_t base = ((size_t)p * NOUT + NPTS) * NOUT;
        for (int m = tid; m < NOUT; m += 256) {
            float v = (m < NPTS) ? lsN1[m] : 0.f;
            __stcs(out + base + m, v);
        }
        return;
    }

    __shared__ float2 scc[NPTS];   // (colActive, lsP1 - colLse), 16 KB
    __shared__ float2 srr[RPB];
    __shared__ float  slsN0[RPB];

    const int r0 = blockIdx.x * RPB;
    const int* m1 = mask + (size_t)(2 * p + 1) * NPTS;
    const float* lsP1 = g_lsP + (size_t)(2 * p + 1) * NPTS;

    #pragma unroll
    for (int i = 0; i < NPTS / 256; i++) {
        int m = tid + 256 * i;
        int a1 = m1[m];
        float lse = a1 ? __logf(g_colS[p * NPTS + m]) : LOG_N;
        scc[m] = make_float2(a1 ? 1.f : 0.f, lsP1[m] - lse);
    }
    if (tid < RPB) {
        int n = r0 + tid;
        int a0 = mask[(size_t)(2 * p) * NPTS + n];
        float lse = a0 ? __logf(g_rowS[p * NPTS + n]) : LOG_N;
        srr[tid] = make_float2(a0 ? 1.f : 0.f, g_lsP[(size_t)(2 * p) * NPTS + n] - lse);
        slsN0[tid] = g_lsN[(size_t)(2 * p) * NPTS + n];
    }
    __syncthreads();

    #pragma unroll
    for (int r = 0; r < RPB; r++) {
        const int n = r0 + r;
        const float2 rr = srr[r];
        const unsigned* Sw = (const unsigned*)(g_Sh + ((size_t)p * NPTS + n) * NPTS);  // 1024 bf16x2
        float* orow = out + ((size_t)p * NOUT + n) * NOUT;
        const bool even = ((((size_t)p * NOUT + n) * NOUT) & 1) == 0;

        #pragma unroll
        for (int i = 0; i < NPTS / 512; i++) {       // 4 iterations, pair index j
            int j = tid + 256 * i;
            unsigned w = __ldcs(Sw + j);
            // bf16 -> f32 by bit shift (exact, incl. -inf masked entries)
            float s0 = __uint_as_float(w << 16);
            float s1 = __uint_as_float(w & 0xFFFF0000u);
            s0 = fmaxf(s0, -FLT_MAX);
            s1 = fmaxf(s1, -FLT_MAX);
            float4 cp = *(const float4*)&scc[2 * j];  // conflict-free LDS.128
            float o0 = fmaf(rr.x + cp.x, s0, rr.y + cp.y);
            float o1 = fmaf(rr.x + cp.z, s1, rr.y + cp.w);
            if (even) {
                float2 o = make_float2(o0, o1);
                __stcs((float2*)orow + j, o);
            } else {
                __stcs(orow + 2 * j, o0);
                __stcs(orow + 2 * j + 1, o1);
            }
        }
        if (tid == 0) __stcs(orow + NPTS, slsN0[r]);
    }
}

// ---------------- launch ----------------
extern "C" void kernel_launch(void* const* d_in, const int* in_sizes, int n_in,
                              void* d_out, int out_size) {
    const float* descriptors = (const float*)d_in[0];
    const int*   mask        = (const int*)d_in[1];
    const float* proj_w      = (const float*)d_in[2];
    const float* proj_b      = (const float*)d_in[3];
    const float* match_w     = (const float*)d_in[4];
    const float* match_b     = (const float*)d_in[5];
    float* out = (float*)d_out;

    proj_gemm<<<dim3(DIM / BN, (BATCH * NPTS) / BM, 1), 256>>>(descriptors, proj_w, proj_b);
    match_kernel<<<(BATCH * NPTS) / 8, 256>>>(descriptors, match_w, match_b);
    sim_gemm<<<dim3(NPTS / BN, NPTS / BM, PAIRS), 256>>>(mask);
    final_kernel<<<dim3(NPTS / RPB + 1, PAIRS), 256>>>(mask, out);
}